// round 13
// baseline (speedup 1.0000x reference)
#include <cuda_runtime.h>

typedef unsigned long long ull;

#define WP_STRIDE 68
#define G_STRIDE 116
#define ROWS 8

// shared layout (float offsets)
#define OFF_WP 0            // 112*68 = 7616
#define OFF_G  7616         // 64*116 = 7424
#define OFF_BP 15040        // 116
#define OFF_BC 15156        // 64
#define OFF_Q  15220        // 16*8*68 = 8704
#define OFF_PR 23924        // 16*8*116 = 14848
#define SMEM_FLOATS 38772   // 155088 bytes -> 1 block/SM

__device__ __align__(16) float g_G[64 * G_STRIDE];

static __device__ __forceinline__ float2 upk(ull v) {
    float2 r; asm("mov.b64 {%0,%1}, %2;" : "=f"(r.x), "=f"(r.y) : "l"(v)); return r;
}
static __device__ __forceinline__ ull fma2(ull a, ull b, ull c) {
    ull d; asm("fma.rn.f32x2 %0, %1, %2, %3;" : "=l"(d) : "l"(a), "l"(b), "l"(c)); return d;
}
static __device__ __forceinline__ float dot4(float4 a, float4 b) {
    float d = a.x * b.x; d = fmaf(a.y, b.y, d); d = fmaf(a.z, b.z, d); d = fmaf(a.w, b.w, d); return d;
}
static __device__ __forceinline__ float2 rx(float2 v, int m) {
    v.x += __shfl_xor_sync(0xffffffffu, v.x, m);
    v.y += __shfl_xor_sync(0xffffffffu, v.y, m);
    return v;
}
static __device__ __forceinline__ float4 rx4(float4 v, int m) {
    v.x += __shfl_xor_sync(0xffffffffu, v.x, m);
    v.y += __shfl_xor_sync(0xffffffffu, v.y, m);
    v.z += __shfl_xor_sync(0xffffffffu, v.z, m);
    v.w += __shfl_xor_sync(0xffffffffu, v.w, m);
    return v;
}
static __device__ __forceinline__ float rsum(float v, int m) {
    return v + __shfl_xor_sync(0xffffffffu, v, m);
}
static __device__ __forceinline__ float rmax(float v, int m) {
    return fmaxf(v, __shfl_xor_sync(0xffffffffu, v, m));
}

// G[n][m]: m<64: (Wc@Wu0)[n][m]; 64..95: Wc@Wu1; 96..111: Wc@Wu2;
// 112..114: Wc@bu_t; 115: 0
__global__ void build_G_kernel(const float* __restrict__ Wc,
                               const float* __restrict__ Wu0,
                               const float* __restrict__ Wu1,
                               const float* __restrict__ Wu2,
                               const float* __restrict__ bu0,
                               const float* __restrict__ bu1,
                               const float* __restrict__ bu2)
{
    int n = blockIdx.x, m = threadIdx.x;
    if (m >= G_STRIDE) return;
    const float* wcn = Wc + n * 64;
    float s = 0.0f;
    if (m < 64)       { for (int h = 0; h < 64; h++) s = fmaf(wcn[h], Wu0[h * 64 + m],      s); }
    else if (m < 96)  { for (int h = 0; h < 64; h++) s = fmaf(wcn[h], Wu1[h * 32 + (m-64)], s); }
    else if (m < 112) { for (int h = 0; h < 64; h++) s = fmaf(wcn[h], Wu2[h * 16 + (m-96)], s); }
    else if (m == 112){ for (int h = 0; h < 64; h++) s = fmaf(wcn[h], bu0[h], s); }
    else if (m == 113){ for (int h = 0; h < 64; h++) s = fmaf(wcn[h], bu1[h], s); }
    else if (m == 114){ for (int h = 0; h < 64; h++) s = fmaf(wcn[h], bu2[h], s); }
    g_G[n * G_STRIDE + m] = s;
}

__global__ void __launch_bounds__(512, 1)
retr_kernel(const float* __restrict__ q,
            const float* __restrict__ mem0,
            const float* __restrict__ mem1,
            const float* __restrict__ mem2,
            const float* __restrict__ Wp0,
            const float* __restrict__ Wp1,
            const float* __restrict__ Wp2,
            const float* __restrict__ bp0,
            const float* __restrict__ bp1,
            const float* __restrict__ bp2,
            const float* __restrict__ bc,
            float* __restrict__ out)
{
    extern __shared__ float sh[];
    const int tid = threadIdx.x, lane = tid & 31, warp = tid >> 5;

    // ---- block init ----
    #pragma unroll 1
    for (int i = tid; i < 112 * 16; i += 512) {
        int row = i >> 4, c4 = (i & 15) << 2;
        const float* src = (row < 64) ? (Wp0 + row * 64)
                         : (row < 96) ? (Wp1 + (row - 64) * 64)
                                      : (Wp2 + (row - 96) * 64);
        *(float4*)(sh + OFF_WP + row * WP_STRIDE + c4) = *(const float4*)(src + c4);
    }
    #pragma unroll 1
    for (int i = tid; i < (64 * G_STRIDE) / 4; i += 512)
        ((float4*)(sh + OFF_G))[i] = ((const float4*)g_G)[i];
    if (tid < 112)
        sh[OFF_BP + tid] = (tid < 64) ? bp0[tid] : (tid < 96) ? bp1[tid - 64] : bp2[tid - 96];
    if (tid < 64) sh[OFF_BC + tid] = bc[tid];
    __syncthreads();

    const int rowbase = blockIdx.x * 128 + warp * ROWS;
    float* sQw = sh + OFF_Q  + warp * ROWS * WP_STRIDE;
    float* sPR = sh + OFF_PR + warp * ROWS * G_STRIDE;

    // stage q tile: 8 rows * 64 floats = 128 float4
    {
        const float4* qg = (const float4*)(q + (size_t)rowbase * 64);
        #pragma unroll
        for (int i = 0; i < 4; i++) {
            int idx = lane + i * 32;
            *(float4*)(sQw + (idx >> 4) * WP_STRIDE + (idx & 15) * 4) = qg[idx];
        }
    }
    __syncwarp();

    // pre-issue stage2 row-0 mem loads (hide DRAM under stage1)
    const float* m0p = mem0 + (size_t)rowbase * 256 + 4 * lane;
    const float* m1p = mem1 + (size_t)rowbase * 256 + 4 * lane;
    const float* m2p = mem2 + (size_t)rowbase * 256 + 4 * lane;
    float4 n0a = *(const float4*)m0p, n0b = *(const float4*)(m0p + 128);
    float4 n1a = *(const float4*)m1p, n1b = *(const float4*)(m1p + 128);
    float4 n2a = *(const float4*)m2p, n2b = *(const float4*)(m2p + 128);

    // ---- stage 1: qp = q @ Wp^T + bp (two column passes) ----
    #pragma unroll 1
    for (int pass = 0; pass < 2; pass++) {
        int cA = pass ? lane + 64 : lane;
        int cB = pass ? 96 + (lane & 15) : lane + 32;
        bool wB = (pass == 0) || (lane < 16);
        ull accA[ROWS], accB[ROWS];
        #pragma unroll
        for (int r = 0; r < ROWS; r++) { accA[r] = 0ull; accB[r] = 0ull; }
        #pragma unroll
        for (int kq = 0; kq < 16; kq++) {
            ulonglong2 wa = *(const ulonglong2*)(sh + OFF_WP + cA * WP_STRIDE + kq * 4);
            ulonglong2 wb = *(const ulonglong2*)(sh + OFF_WP + cB * WP_STRIDE + kq * 4);
            #pragma unroll
            for (int r = 0; r < ROWS; r++) {
                ulonglong2 qv = *(const ulonglong2*)(sQw + r * WP_STRIDE + kq * 4);
                accA[r] = fma2(wa.x, qv.x, accA[r]);
                accA[r] = fma2(wa.y, qv.y, accA[r]);
                accB[r] = fma2(wb.x, qv.x, accB[r]);
                accB[r] = fma2(wb.y, qv.y, accB[r]);
            }
        }
        float ba = sh[OFF_BP + cA], bb = sh[OFF_BP + cB];
        #pragma unroll
        for (int r = 0; r < ROWS; r++) {
            float2 a = upk(accA[r]);
            sPR[r * G_STRIDE + cA] = a.x + a.y + ba;
            if (wB) { float2 b2 = upk(accB[r]); sPR[r * G_STRIDE + cB] = b2.x + b2.y + bb; }
        }
    }
    __syncwarp();

    // ---- stage 2: per-row sims/softmax/retrieval (register-lean, prefetch) ----
    #pragma unroll 1
    for (int r = 0; r < ROWS; r++) {
        float4 v0a = n0a, v0b = n0b, v1a = n1a, v1b = n1b, v2a = n2a, v2b = n2b;
        if (r < ROWS - 1) {
            const float* a0 = m0p + (r + 1) * 256;
            const float* a1 = m1p + (r + 1) * 256;
            const float* a2 = m2p + (r + 1) * 256;
            n0a = *(const float4*)a0; n0b = *(const float4*)(a0 + 128);
            n1a = *(const float4*)a1; n1b = *(const float4*)(a1 + 128);
            n2a = *(const float4*)a2; n2b = *(const float4*)(a2 + 128);
        }
        float* pr = sPR + r * G_STRIDE;
        float4 qp0 = *(const float4*)(pr + 4 * (lane & 15));
        float4 qp1 = *(const float4*)(pr + 64 + 4 * (lane & 7));
        float4 qp2 = *(const float4*)(pr + 96 + 4 * (lane & 3));

        // tier 0
        float2 s0 = make_float2(dot4(v0a, qp0), dot4(v0b, qp0));
        s0 = rx(s0, 1); s0 = rx(s0, 2); s0 = rx(s0, 4); s0 = rx(s0, 8);
        float e0x = __expf(s0.x * 0.125f), e0y = __expf(s0.y * 0.125f);
        float p0 = rsum(e0x + e0y, 16);
        float m0v = rmax(fmaxf(e0x, e0y), 16);
        float4 u0 = make_float4(e0x * v0a.x + e0y * v0b.x, e0x * v0a.y + e0y * v0b.y,
                                e0x * v0a.z + e0y * v0b.z, e0x * v0a.w + e0y * v0b.w);
        u0 = rx4(u0, 16);

        // tier 1
        float2 s1 = make_float2(dot4(v1a, qp1), dot4(v1b, qp1));
        s1 = rx(s1, 1); s1 = rx(s1, 2); s1 = rx(s1, 4);
        float e1x = __expf(s1.x * 0.17677669529663689f), e1y = __expf(s1.y * 0.17677669529663689f);
        float p1 = rsum(rsum(e1x + e1y, 8), 16);
        float m1v = rmax(rmax(fmaxf(e1x, e1y), 8), 16);
        float4 u1 = make_float4(e1x * v1a.x + e1y * v1b.x, e1x * v1a.y + e1y * v1b.y,
                                e1x * v1a.z + e1y * v1b.z, e1x * v1a.w + e1y * v1b.w);
        u1 = rx4(u1, 8); u1 = rx4(u1, 16);

        // tier 2
        float2 s2 = make_float2(dot4(v2a, qp2), dot4(v2b, qp2));
        s2 = rx(s2, 1); s2 = rx(s2, 2);
        float e2x = __expf(s2.x * 0.25f), e2y = __expf(s2.y * 0.25f);
        float p2 = rsum(rsum(rsum(e2x + e2y, 4), 8), 16);
        float m2v = rmax(rmax(rmax(fmaxf(e2x, e2y), 4), 8), 16);
        float4 u2 = make_float4(e2x * v2a.x + e2y * v2b.x, e2x * v2a.y + e2y * v2b.y,
                                e2x * v2a.z + e2y * v2b.z, e2x * v2a.w + e2y * v2b.w);
        u2 = rx4(u2, 4); u2 = rx4(u2, 8); u2 = rx4(u2, 16);

        // confidence coupling
        float i0 = __fdividef(1.0f, p0), i1 = __fdividef(1.0f, p1), i2 = __fdividef(1.0f, p2);
        float ec0 = __expf(m0v * i0), ec1 = __expf(m1v * i1), ec2 = __expf(m2v * i2);
        float ci = __fdividef(1.0f, ec0 + ec1 + ec2);
        float c0 = ec0 * ci, c1 = ec1 * ci, c2 = ec2 * ci;
        float k0 = c0 * i0, k1 = c1 * i1, k2 = c2 * i2;

        if (lane < 16)
            *(float4*)(pr + 4 * lane) =
                make_float4(k0 * u0.x, k0 * u0.y, k0 * u0.z, k0 * u0.w);
        if (lane < 8)
            *(float4*)(pr + 64 + 4 * lane) =
                make_float4(k1 * u1.x, k1 * u1.y, k1 * u1.z, k1 * u1.w);
        if (lane < 4)
            *(float4*)(pr + 96 + 4 * lane) =
                make_float4(k2 * u2.x, k2 * u2.y, k2 * u2.z, k2 * u2.w);
        if (lane == 0) *(float4*)(pr + 112) = make_float4(c0, c1, c2, 0.0f);
    }
    __syncwarp();

    // ---- stage 3: out = r @ G^T + bc ----
    {
        int nA = lane, nB = lane + 32;
        ull accA[ROWS], accB[ROWS];
        #pragma unroll
        for (int r = 0; r < ROWS; r++) { accA[r] = 0ull; accB[r] = 0ull; }
        const float* gA = sh + OFF_G + nA * G_STRIDE;
        const float* gB = sh + OFF_G + nB * G_STRIDE;
        #pragma unroll 2
        for (int jq = 0; jq < 29; jq++) {
            ulonglong2 ga = *(const ulonglong2*)(gA + jq * 4);
            ulonglong2 gb = *(const ulonglong2*)(gB + jq * 4);
            #pragma unroll
            for (int r = 0; r < ROWS; r++) {
                ulonglong2 rv = *(const ulonglong2*)(sPR + r * G_STRIDE + jq * 4);
                accA[r] = fma2(ga.x, rv.x, accA[r]);
                accA[r] = fma2(ga.y, rv.y, accA[r]);
                accB[r] = fma2(gb.x, rv.x, accB[r]);
                accB[r] = fma2(gb.y, rv.y, accB[r]);
            }
        }
        float bA = sh[OFF_BC + nA], bB = sh[OFF_BC + nB];
        #pragma unroll
        for (int r = 0; r < ROWS; r++) {
            float2 a = upk(accA[r]);
            float2 b = upk(accB[r]);
            size_t o = (size_t)(rowbase + r) * 64;
            out[o + nA] = a.x + a.y + bA;
            out[o + nB] = b.x + b.y + bB;
        }
    }
}

extern "C" void kernel_launch(void* const* d_in, const int* in_sizes, int n_in,
                              void* d_out, int out_size)
{
    (void)n_in; (void)out_size;
    const float* q    = (const float*)d_in[0];
    const float* mem0 = (const float*)d_in[1];
    const float* mem1 = (const float*)d_in[2];
    const float* mem2 = (const float*)d_in[3];
    const float *Wp0, *bp0, *Wp1, *bp1, *Wp2, *bp2;
    const float *Wu0, *bu0, *Wu1, *bu1, *Wu2, *bu2;
    if (in_sizes[6] == 64 * 64) {
        // dict insertion order: Wp0,bp0,Wu0,bu0, Wp1,bp1,Wu1,bu1, Wp2,bp2,Wu2,bu2
        Wp0 = (const float*)d_in[4];  bp0 = (const float*)d_in[5];
        Wu0 = (const float*)d_in[6];  bu0 = (const float*)d_in[7];
        Wp1 = (const float*)d_in[8];  bp1 = (const float*)d_in[9];
        Wu1 = (const float*)d_in[10]; bu1 = (const float*)d_in[11];
        Wp2 = (const float*)d_in[12]; bp2 = (const float*)d_in[13];
        Wu2 = (const float*)d_in[14]; bu2 = (const float*)d_in[15];
    } else {
        // signature order: Wp0,bp0,Wp1,bp1,Wp2,bp2, Wu0,bu0,Wu1,bu1,Wu2,bu2
        Wp0 = (const float*)d_in[4];  bp0 = (const float*)d_in[5];
        Wp1 = (const float*)d_in[6];  bp1 = (const float*)d_in[7];
        Wp2 = (const float*)d_in[8];  bp2 = (const float*)d_in[9];
        Wu0 = (const float*)d_in[10]; bu0 = (const float*)d_in[11];
        Wu1 = (const float*)d_in[12]; bu1 = (const float*)d_in[13];
        Wu2 = (const float*)d_in[14]; bu2 = (const float*)d_in[15];
    }
    const float* Wc = (const float*)d_in[16];
    const float* bc = (const float*)d_in[17];
    int B = in_sizes[0] / 64;

    build_G_kernel<<<64, 128>>>(Wc, Wu0, Wu1, Wu2, bu0, bu1, bu2);

    cudaFuncSetAttribute(retr_kernel, cudaFuncAttributeMaxDynamicSharedMemorySize,
                         SMEM_FLOATS * sizeof(float));
    retr_kernel<<<B / 128, 512, SMEM_FLOATS * sizeof(float)>>>(
        q, mem0, mem1, mem2, Wp0, Wp1, Wp2, bp0, bp1, bp2, bc, (float*)d_out);
}

// round 14
// speedup vs baseline: 5.3715x; 5.3715x over previous
#include <cuda_runtime.h>

typedef unsigned long long ull;

#define WP_STRIDE 68
#define G_STRIDE 116
#define ROWS 8

// shared layout (float offsets)
#define OFF_WP 0            // 112*68 = 7616
#define OFF_G  7616         // 64*116 = 7424
#define OFF_BP 15040        // 116
#define OFF_BC 15156        // 64
#define OFF_Q  15220        // 16*8*68 = 8704
#define OFF_PR 23924        // 16*8*116 = 14848
#define SMEM_FLOATS 38772   // 155088 bytes -> 1 block/SM

__device__ __align__(16) float g_G[64 * G_STRIDE];

static __device__ __forceinline__ float2 upk(ull v) {
    float2 r; asm("mov.b64 {%0,%1}, %2;" : "=f"(r.x), "=f"(r.y) : "l"(v)); return r;
}
static __device__ __forceinline__ ull fma2(ull a, ull b, ull c) {
    ull d; asm("fma.rn.f32x2 %0, %1, %2, %3;" : "=l"(d) : "l"(a), "l"(b), "l"(c)); return d;
}
static __device__ __forceinline__ float dot4(float4 a, float4 b) {
    float d = a.x * b.x; d = fmaf(a.y, b.y, d); d = fmaf(a.z, b.z, d); d = fmaf(a.w, b.w, d); return d;
}
static __device__ __forceinline__ float2 rx(float2 v, int m) {
    v.x += __shfl_xor_sync(0xffffffffu, v.x, m);
    v.y += __shfl_xor_sync(0xffffffffu, v.y, m);
    return v;
}
static __device__ __forceinline__ float4 rx4(float4 v, int m) {
    v.x += __shfl_xor_sync(0xffffffffu, v.x, m);
    v.y += __shfl_xor_sync(0xffffffffu, v.y, m);
    v.z += __shfl_xor_sync(0xffffffffu, v.z, m);
    v.w += __shfl_xor_sync(0xffffffffu, v.w, m);
    return v;
}
static __device__ __forceinline__ float rsum(float v, int m) {
    return v + __shfl_xor_sync(0xffffffffu, v, m);
}
static __device__ __forceinline__ float rmax(float v, int m) {
    return fmaxf(v, __shfl_xor_sync(0xffffffffu, v, m));
}

// G[n][m]: m<64: (Wc@Wu0)[n][m]; 64..95: Wc@Wu1; 96..111: Wc@Wu2;
// 112..114: Wc@bu_t; 115: 0
__global__ void build_G_kernel(const float* __restrict__ Wc,
                               const float* __restrict__ Wu0,
                               const float* __restrict__ Wu1,
                               const float* __restrict__ Wu2,
                               const float* __restrict__ bu0,
                               const float* __restrict__ bu1,
                               const float* __restrict__ bu2)
{
    int n = blockIdx.x, m = threadIdx.x;
    if (m >= G_STRIDE) return;
    const float* wcn = Wc + n * 64;
    float s = 0.0f;
    if (m < 64)       { for (int h = 0; h < 64; h++) s = fmaf(wcn[h], Wu0[h * 64 + m],      s); }
    else if (m < 96)  { for (int h = 0; h < 64; h++) s = fmaf(wcn[h], Wu1[h * 32 + (m-64)], s); }
    else if (m < 112) { for (int h = 0; h < 64; h++) s = fmaf(wcn[h], Wu2[h * 16 + (m-96)], s); }
    else if (m == 112){ for (int h = 0; h < 64; h++) s = fmaf(wcn[h], bu0[h], s); }
    else if (m == 113){ for (int h = 0; h < 64; h++) s = fmaf(wcn[h], bu1[h], s); }
    else if (m == 114){ for (int h = 0; h < 64; h++) s = fmaf(wcn[h], bu2[h], s); }
    g_G[n * G_STRIDE + m] = s;
}

__global__ void __launch_bounds__(512, 1)
retr_kernel(const float* __restrict__ q,
            const float* __restrict__ mem0,
            const float* __restrict__ mem1,
            const float* __restrict__ mem2,
            const float* __restrict__ Wp0,
            const float* __restrict__ Wp1,
            const float* __restrict__ Wp2,
            const float* __restrict__ bp0,
            const float* __restrict__ bp1,
            const float* __restrict__ bp2,
            const float* __restrict__ bc,
            float* __restrict__ out)
{
    extern __shared__ float sh[];
    const int tid = threadIdx.x, lane = tid & 31, warp = tid >> 5;

    // ---- block init ----
    #pragma unroll 1
    for (int i = tid; i < 112 * 16; i += 512) {
        int row = i >> 4, c4 = (i & 15) << 2;
        const float* src = (row < 64) ? (Wp0 + row * 64)
                         : (row < 96) ? (Wp1 + (row - 64) * 64)
                                      : (Wp2 + (row - 96) * 64);
        *(float4*)(sh + OFF_WP + row * WP_STRIDE + c4) = *(const float4*)(src + c4);
    }
    #pragma unroll 1
    for (int i = tid; i < (64 * G_STRIDE) / 4; i += 512)
        ((float4*)(sh + OFF_G))[i] = ((const float4*)g_G)[i];
    if (tid < 112)
        sh[OFF_BP + tid] = (tid < 64) ? bp0[tid] : (tid < 96) ? bp1[tid - 64] : bp2[tid - 96];
    if (tid < 64) sh[OFF_BC + tid] = bc[tid];
    __syncthreads();

    const int rowbase = blockIdx.x * 128 + warp * ROWS;
    float* sQw = sh + OFF_Q  + warp * ROWS * WP_STRIDE;
    float* sPR = sh + OFF_PR + warp * ROWS * G_STRIDE;

    // stage q tile: 8 rows * 64 floats = 128 float4
    {
        const float4* qg = (const float4*)(q + (size_t)rowbase * 64);
        #pragma unroll
        for (int i = 0; i < 4; i++) {
            int idx = lane + i * 32;
            *(float4*)(sQw + (idx >> 4) * WP_STRIDE + (idx & 15) * 4) = qg[idx];
        }
    }
    __syncwarp();

    // pre-issue stage2 row-0 mem loads (hide DRAM under stage1)
    const float* m0p = mem0 + (size_t)rowbase * 256 + 4 * lane;
    const float* m1p = mem1 + (size_t)rowbase * 256 + 4 * lane;
    const float* m2p = mem2 + (size_t)rowbase * 256 + 4 * lane;
    float4 n0a = *(const float4*)m0p, n0b = *(const float4*)(m0p + 128);
    float4 n1a = *(const float4*)m1p, n1b = *(const float4*)(m1p + 128);
    float4 n2a = *(const float4*)m2p, n2b = *(const float4*)(m2p + 128);

    // ---- stage 1: qp = q @ Wp^T + bp (two column passes) ----
    #pragma unroll 1
    for (int pass = 0; pass < 2; pass++) {
        int cA = pass ? lane + 64 : lane;
        int cB = pass ? 96 + (lane & 15) : lane + 32;
        bool wB = (pass == 0) || (lane < 16);
        ull accA[ROWS], accB[ROWS];
        #pragma unroll
        for (int r = 0; r < ROWS; r++) { accA[r] = 0ull; accB[r] = 0ull; }
        #pragma unroll 4
        for (int kq = 0; kq < 16; kq++) {
            ulonglong2 wa = *(const ulonglong2*)(sh + OFF_WP + cA * WP_STRIDE + kq * 4);
            ulonglong2 wb = *(const ulonglong2*)(sh + OFF_WP + cB * WP_STRIDE + kq * 4);
            #pragma unroll
            for (int r = 0; r < ROWS; r++) {
                ulonglong2 qv = *(const ulonglong2*)(sQw + r * WP_STRIDE + kq * 4);
                accA[r] = fma2(wa.x, qv.x, accA[r]);
                accA[r] = fma2(wa.y, qv.y, accA[r]);
                accB[r] = fma2(wb.x, qv.x, accB[r]);
                accB[r] = fma2(wb.y, qv.y, accB[r]);
            }
        }
        float ba = sh[OFF_BP + cA], bb = sh[OFF_BP + cB];
        #pragma unroll
        for (int r = 0; r < ROWS; r++) {
            float2 a = upk(accA[r]);
            sPR[r * G_STRIDE + cA] = a.x + a.y + ba;
            if (wB) { float2 b2 = upk(accB[r]); sPR[r * G_STRIDE + cB] = b2.x + b2.y + bb; }
        }
    }
    __syncwarp();

    // ---- stage 2: per-row sims/softmax/retrieval (register-lean, prefetch) ----
    #pragma unroll 1
    for (int r = 0; r < ROWS; r++) {
        float4 v0a = n0a, v0b = n0b, v1a = n1a, v1b = n1b, v2a = n2a, v2b = n2b;
        if (r < ROWS - 1) {
            const float* a0 = m0p + (r + 1) * 256;
            const float* a1 = m1p + (r + 1) * 256;
            const float* a2 = m2p + (r + 1) * 256;
            n0a = *(const float4*)a0; n0b = *(const float4*)(a0 + 128);
            n1a = *(const float4*)a1; n1b = *(const float4*)(a1 + 128);
            n2a = *(const float4*)a2; n2b = *(const float4*)(a2 + 128);
        }
        float* pr = sPR + r * G_STRIDE;
        float4 qp0 = *(const float4*)(pr + 4 * (lane & 15));
        float4 qp1 = *(const float4*)(pr + 64 + 4 * (lane & 7));
        float4 qp2 = *(const float4*)(pr + 96 + 4 * (lane & 3));

        // tier 0
        float2 s0 = make_float2(dot4(v0a, qp0), dot4(v0b, qp0));
        s0 = rx(s0, 1); s0 = rx(s0, 2); s0 = rx(s0, 4); s0 = rx(s0, 8);
        float e0x = __expf(s0.x * 0.125f), e0y = __expf(s0.y * 0.125f);
        float p0 = rsum(e0x + e0y, 16);
        float m0v = rmax(fmaxf(e0x, e0y), 16);
        float4 u0 = make_float4(e0x * v0a.x + e0y * v0b.x, e0x * v0a.y + e0y * v0b.y,
                                e0x * v0a.z + e0y * v0b.z, e0x * v0a.w + e0y * v0b.w);
        u0 = rx4(u0, 16);

        // tier 1
        float2 s1 = make_float2(dot4(v1a, qp1), dot4(v1b, qp1));
        s1 = rx(s1, 1); s1 = rx(s1, 2); s1 = rx(s1, 4);
        float e1x = __expf(s1.x * 0.17677669529663689f), e1y = __expf(s1.y * 0.17677669529663689f);
        float p1 = rsum(rsum(e1x + e1y, 8), 16);
        float m1v = rmax(rmax(fmaxf(e1x, e1y), 8), 16);
        float4 u1 = make_float4(e1x * v1a.x + e1y * v1b.x, e1x * v1a.y + e1y * v1b.y,
                                e1x * v1a.z + e1y * v1b.z, e1x * v1a.w + e1y * v1b.w);
        u1 = rx4(u1, 8); u1 = rx4(u1, 16);

        // tier 2
        float2 s2 = make_float2(dot4(v2a, qp2), dot4(v2b, qp2));
        s2 = rx(s2, 1); s2 = rx(s2, 2);
        float e2x = __expf(s2.x * 0.25f), e2y = __expf(s2.y * 0.25f);
        float p2 = rsum(rsum(rsum(e2x + e2y, 4), 8), 16);
        float m2v = rmax(rmax(rmax(fmaxf(e2x, e2y), 4), 8), 16);
        float4 u2 = make_float4(e2x * v2a.x + e2y * v2b.x, e2x * v2a.y + e2y * v2b.y,
                                e2x * v2a.z + e2y * v2b.z, e2x * v2a.w + e2y * v2b.w);
        u2 = rx4(u2, 4); u2 = rx4(u2, 8); u2 = rx4(u2, 16);

        // confidence coupling
        float i0 = __fdividef(1.0f, p0), i1 = __fdividef(1.0f, p1), i2 = __fdividef(1.0f, p2);
        float ec0 = __expf(m0v * i0), ec1 = __expf(m1v * i1), ec2 = __expf(m2v * i2);
        float ci = __fdividef(1.0f, ec0 + ec1 + ec2);
        float c0 = ec0 * ci, c1 = ec1 * ci, c2 = ec2 * ci;
        float k0 = c0 * i0, k1 = c1 * i1, k2 = c2 * i2;

        if (lane < 16)
            *(float4*)(pr + 4 * lane) =
                make_float4(k0 * u0.x, k0 * u0.y, k0 * u0.z, k0 * u0.w);
        if (lane < 8)
            *(float4*)(pr + 64 + 4 * lane) =
                make_float4(k1 * u1.x, k1 * u1.y, k1 * u1.z, k1 * u1.w);
        if (lane < 4)
            *(float4*)(pr + 96 + 4 * lane) =
                make_float4(k2 * u2.x, k2 * u2.y, k2 * u2.z, k2 * u2.w);
        if (lane == 0) *(float4*)(pr + 112) = make_float4(c0, c1, c2, 0.0f);
    }
    __syncwarp();

    // ---- stage 3: out = r @ G^T + bc ----
    {
        int nA = lane, nB = lane + 32;
        ull accA[ROWS], accB[ROWS];
        #pragma unroll
        for (int r = 0; r < ROWS; r++) { accA[r] = 0ull; accB[r] = 0ull; }
        const float* gA = sh + OFF_G + nA * G_STRIDE;
        const float* gB = sh + OFF_G + nB * G_STRIDE;
        #pragma unroll 2
        for (int jq = 0; jq < 29; jq++) {
            ulonglong2 ga = *(const ulonglong2*)(gA + jq * 4);
            ulonglong2 gb = *(const ulonglong2*)(gB + jq * 4);
            #pragma unroll
            for (int r = 0; r < ROWS; r++) {
                ulonglong2 rv = *(const ulonglong2*)(sPR + r * G_STRIDE + jq * 4);
                accA[r] = fma2(ga.x, rv.x, accA[r]);
                accA[r] = fma2(ga.y, rv.y, accA[r]);
                accB[r] = fma2(gb.x, rv.x, accB[r]);
                accB[r] = fma2(gb.y, rv.y, accB[r]);
            }
        }
        float bA = sh[OFF_BC + nA], bB = sh[OFF_BC + nB];
        #pragma unroll
        for (int r = 0; r < ROWS; r++) {
            float2 a = upk(accA[r]);
            float2 b = upk(accB[r]);
            size_t o = (size_t)(rowbase + r) * 64;
            out[o + nA] = a.x + a.y + bA;
            out[o + nB] = b.x + b.y + bB;
        }
    }
}

extern "C" void kernel_launch(void* const* d_in, const int* in_sizes, int n_in,
                              void* d_out, int out_size)
{
    (void)n_in; (void)out_size;
    const float* q    = (const float*)d_in[0];
    const float* mem0 = (const float*)d_in[1];
    const float* mem1 = (const float*)d_in[2];
    const float* mem2 = (const float*)d_in[3];
    const float *Wp0, *bp0, *Wp1, *bp1, *Wp2, *bp2;
    const float *Wu0, *bu0, *Wu1, *bu1, *Wu2, *bu2;
    if (in_sizes[6] == 64 * 64) {
        // dict insertion order: Wp0,bp0,Wu0,bu0, Wp1,bp1,Wu1,bu1, Wp2,bp2,Wu2,bu2
        Wp0 = (const float*)d_in[4];  bp0 = (const float*)d_in[5];
        Wu0 = (const float*)d_in[6];  bu0 = (const float*)d_in[7];
        Wp1 = (const float*)d_in[8];  bp1 = (const float*)d_in[9];
        Wu1 = (const float*)d_in[10]; bu1 = (const float*)d_in[11];
        Wp2 = (const float*)d_in[12]; bp2 = (const float*)d_in[13];
        Wu2 = (const float*)d_in[14]; bu2 = (const float*)d_in[15];
    } else {
        // signature order: Wp0,bp0,Wp1,bp1,Wp2,bp2, Wu0,bu0,Wu1,bu1,Wu2,bu2
        Wp0 = (const float*)d_in[4];  bp0 = (const float*)d_in[5];
        Wp1 = (const float*)d_in[6];  bp1 = (const float*)d_in[7];
        Wp2 = (const float*)d_in[8];  bp2 = (const float*)d_in[9];
        Wu0 = (const float*)d_in[10]; bu0 = (const float*)d_in[11];
        Wu1 = (const float*)d_in[12]; bu1 = (const float*)d_in[13];
        Wu2 = (const float*)d_in[14]; bu2 = (const float*)d_in[15];
    }
    const float* Wc = (const float*)d_in[16];
    const float* bc = (const float*)d_in[17];
    int B = in_sizes[0] / 64;

    build_G_kernel<<<64, 128>>>(Wc, Wu0, Wu1, Wu2, bu0, bu1, bu2);

    cudaFuncSetAttribute(retr_kernel, cudaFuncAttributeMaxDynamicSharedMemorySize,
                         SMEM_FLOATS * sizeof(float));
    retr_kernel<<<B / 128, 512, SMEM_FLOATS * sizeof(float)>>>(
        q, mem0, mem1, mem2, Wp0, Wp1, Wp2, bp0, bp1, bp2, bc, (float*)d_out);
}